// round 17
// baseline (speedup 1.0000x reference)
#include <cuda_runtime.h>
#include <cuda_bf16.h>
#include <cstdint>

// Problem: B=256, N=64, d=64. Outputs concatenated: alphas [B,N,N,1] then value [B,N,N,64].
constexpr int Bn = 256;
constexpr int Nn = 64;
constexpr int Dn = 64;
constexpr float NEG_SLOPE = 0.01f;

// smem layout (bytes)
constexpr int OFF_WB   = 0;                      // 64 f32
constexpr int OFF_AW   = 256;                    // 64 f32
constexpr int OFF_PART = 512;                    // 128 f32 partial logits (2 e-halves x 64)
constexpr int OFF_XI   = 1024;                   // 8 i-rows fp32 stride 72: 2304
constexpr int OFF_XJ   = 3328;                   // 8 j-rows: 2304
constexpr int OFF_EJ   = 5632;                   // EJ frag table (swizzled): 2048
constexpr int OFF_SB   = 7680;                   // W frag table bf16 hi/lo (swizzled): 16384
constexpr int SMEM_TOTAL = OFF_SB + 16384;       // 24064 B

// upper-triangle 8x8-block enumeration (36 blocks)
static __device__ const unsigned char cBI[36] = {
    0,0,0,0,0,0,0,0, 1,1,1,1,1,1,1, 2,2,2,2,2,2, 3,3,3,3,3, 4,4,4,4, 5,5,5, 6,6, 7};
static __device__ const unsigned char cBJ[36] = {
    0,1,2,3,4,5,6,7, 1,2,3,4,5,6,7, 2,3,4,5,6,7, 3,4,5,6,7, 4,5,6,7, 5,6,7, 6,7, 7};

static __device__ __forceinline__ void mma_bf16(float* c, const uint32_t* a, const uint32_t* b) {
    asm volatile(
        "mma.sync.aligned.m16n8k16.row.col.f32.bf16.bf16.f32 "
        "{%0,%1,%2,%3}, {%4,%5,%6,%7}, {%8,%9}, {%0,%1,%2,%3};"
        : "+f"(c[0]), "+f"(c[1]), "+f"(c[2]), "+f"(c[3])
        : "r"(a[0]), "r"(a[1]), "r"(a[2]), "r"(a[3]), "r"(b[0]), "r"(b[1]));
}

static __device__ __forceinline__ void split2(float a, float b, uint32_t& hi, uint32_t& lo) {
    __nv_bfloat162 h = __floats2bfloat162_rn(a, b);
    uint32_t hu = *reinterpret_cast<uint32_t*>(&h);
    float hax = __uint_as_float(hu << 16);
    float hay = __uint_as_float(hu & 0xFFFF0000u);
    __nv_bfloat162 l = __floats2bfloat162_rn(a - hax, b - hay);
    hi = hu;
    lo = *reinterpret_cast<uint32_t*>(&l);
}

static __device__ __forceinline__ void stcs4(float* p, float4 v) {
    asm volatile("st.global.cs.v4.f32 [%0], {%1,%2,%3,%4};"
                 :: "l"(p), "f"(v.x), "f"(v.y), "f"(v.z), "f"(v.w) : "memory");
}

// 64-row frag table swizzle (W table): ks block stride 4096B
static __device__ __forceinline__ uint32_t swzoff(int j, int q, int ks) {
    uint32_t u = (uint32_t)(j * 4 + q);
    uint32_t t = (((uint32_t)j & 3u) << 1) | (((uint32_t)ks >> 1) & 1u);
    return ((uint32_t)ks << 12) + ((u ^ t) << 4);
}
// 8-row frag table swizzle (EJ table): ks block stride 512B
static __device__ __forceinline__ uint32_t swz8(int j, int q, int ks) {
    uint32_t u = (uint32_t)(j * 4 + q);
    uint32_t t = (((uint32_t)j & 3u) << 1) | (((uint32_t)ks >> 1) & 1u);
    return ((uint32_t)ks << 9) + ((u ^ t) << 4);
}

// One CTA: (b, 6 triangle blocks xb*6..xb*6+5), 256 threads / 8 warps, 1 block per pass.
// Warp = (i-pair p = wid>>1, e-half eh = wid&1): M=16 (pair x 8j) x N=32 (e-half) GEMM,
// partial logits summed in smem. Value(+mirror) stores fully coalesced.
__global__ __launch_bounds__(256, 3)
void afm_pair(const float* __restrict__ emb,
              const float* __restrict__ wW,
              const float* __restrict__ wb,
              const float* __restrict__ aW,
              float* __restrict__ logits,   // B*N*N scratch (= alphas buffer)
              float* __restrict__ outV)
{
    extern __shared__ __align__(16) char smem[];
    const int xb  = blockIdx.x;   // 0..5
    const int b   = blockIdx.y;   // 0..255
    const int tx  = threadIdx.x;
    const int wid = tx >> 5;      // 0..7
    const int lid = tx & 31;
    const int g   = lid >> 2;     // 0..7
    const int q   = lid & 3;      // 0..3

    float* sWB = reinterpret_cast<float*>(smem + OFF_WB);
    float* sAW = reinterpret_cast<float*>(smem + OFF_AW);
    float* sPT = reinterpret_cast<float*>(smem + OFF_PART);

    const float* embB = emb + (size_t)b * Nn * Dn;
    const float4* embB4 = reinterpret_cast<const float4*>(embB);

    if (tx < 64) { sWB[tx] = wb[tx]; sAW[tx] = aW[tx]; }

    // ---- W frag table (64 rows), bf16 hi/lo, swizzled — ONCE per CTA ----
    {
        const int jr = tx >> 2;    // 0..63
        const int qt = tx & 3;     // ks block
        const float4* src = reinterpret_cast<const float4*>(wW + jr * Dn + qt * 16);
        uint32_t hu[8], lu[8];
        #pragma unroll
        for (int k = 0; k < 4; k++) {
            float4 w4 = src[k];
            split2(w4.x, w4.y, hu[2 * k],     lu[2 * k]);
            split2(w4.z, w4.w, hu[2 * k + 1], lu[2 * k + 1]);
        }
        #pragma unroll
        for (int qq = 0; qq < 4; qq++) {
            *reinterpret_cast<uint4*>(smem + OFF_SB + swzoff(jr, qq, qt)) =
                make_uint4(hu[qq], hu[qq + 4], lu[qq], lu[qq + 4]);
        }
    }

    #pragma unroll 1
    for (int pp = 0; pp < 6; pp++) {
        const int t  = xb * 6 + pp;   // 0..35
        const int bi = cBI[t];
        const int bj = cBJ[t];
        const bool diag = (bi == bj);

        __syncthreads();   // protect XI/XJ/EJ from previous pass

        // ---- fills ----
        if (tx < 128) {
            const int row = tx >> 4;   // 0..7
            const int c4  = tx & 15;
            reinterpret_cast<float4*>(
                reinterpret_cast<float*>(smem + OFF_XI) + row * 72)[c4] =
                reinterpret_cast<const float4*>(embB + (bi * 8 + row) * Dn)[c4];
            reinterpret_cast<float4*>(
                reinterpret_cast<float*>(smem + OFF_XJ) + row * 72)[c4] =
                reinterpret_cast<const float4*>(embB + (bj * 8 + row) * Dn)[c4];
        }
        if (tx < 32) {   // EJ frag table
            const int row = tx >> 2;   // 0..7
            const int qt  = tx & 3;
            float4 e[4];
            const float4* src = reinterpret_cast<const float4*>(
                embB + (bj * 8 + row) * Dn + qt * 16);
            #pragma unroll
            for (int k = 0; k < 4; k++) e[k] = src[k];
            #pragma unroll
            for (int qq = 0; qq < 4; qq++) {
                float4 va = e[qq >> 1];
                float4 vb = e[2 + (qq >> 1)];
                float ax = (qq & 1) ? va.z : va.x;
                float ay = (qq & 1) ? va.w : va.y;
                float bx = (qq & 1) ? vb.z : vb.x;
                float by = (qq & 1) ? vb.w : vb.y;
                *reinterpret_cast<float4*>(smem + OFF_EJ + swz8(row, qq, qt)) =
                    make_float4(ax, ay, bx, by);
            }
        }
        __syncthreads();

        const float* sXI = reinterpret_cast<const float*>(smem + OFF_XI);

        // ---- value phase: warp -> j row wid; lane = (h = i parity, c = chunk) ----
        {
            const int c = lid & 15;
            const int h = lid >> 4;
            const int jG = bj * 8 + wid;
            const float4 e = embB4[jG * 16 + c];   // broadcast across halves, L1-hot
            #pragma unroll
            for (int Lo = 0; Lo < 4; Lo++) {
                const int i = 2 * Lo + h;
                const int iG = bi * 8 + i;
                const float4 xi = *reinterpret_cast<const float4*>(sXI + i * 72 + c * 4);
                const float4 v = make_float4(e.x * xi.x, e.y * xi.y, e.z * xi.z, e.w * xi.w);
                stcs4(outV + ((((size_t)b * Nn + iG) * Nn + jG) * Dn + c * 4), v);
                if (!diag)
                    stcs4(outV + ((((size_t)b * Nn + jG) * Nn + iG) * Dn + c * 4), v);
            }
        }

        // ---- GEMM: warp (p = wid>>1, eh = wid&1): M=16 x N=32(e-half) x K=64 ----
        {
            const int p   = wid >> 1;
            const int eh  = wid & 1;
            const int nt0 = eh * 4;
            const float* sXi0 = sXI + (2 * p) * 72;
            const float* sXi1 = sXi0 + 72;
            const char*  sEJ  = smem + OFF_EJ;

            float acc[4][4];
            #pragma unroll
            for (int nt = 0; nt < 4; nt++)
                #pragma unroll
                for (int r = 0; r < 4; r++) acc[nt][r] = 0.0f;

            #pragma unroll
            for (int ks = 0; ks < 4; ks++) {
                const int kc = ks * 16 + 2 * q;
                const float2 xa0 = *reinterpret_cast<const float2*>(sXi0 + kc);
                const float2 xc0 = *reinterpret_cast<const float2*>(sXi0 + kc + 8);
                const float2 xa1 = *reinterpret_cast<const float2*>(sXi1 + kc);
                const float2 xc1 = *reinterpret_cast<const float2*>(sXi1 + kc + 8);

                const float4 f0 = *reinterpret_cast<const float4*>(sEJ + swz8(g, q, ks));
                uint32_t ah[4], al[4];
                split2(f0.x * xa0.x, f0.y * xa0.y, ah[0], al[0]);   // row g   (i0), k-lo
                split2(f0.x * xa1.x, f0.y * xa1.y, ah[1], al[1]);   // row g+8 (i1), k-lo
                split2(f0.z * xc0.x, f0.w * xc0.y, ah[2], al[2]);   // row g   (i0), k-hi
                split2(f0.z * xc1.x, f0.w * xc1.y, ah[3], al[3]);   // row g+8 (i1), k-hi

                #pragma unroll
                for (int nt = 0; nt < 4; nt++) {
                    const uint4 bv = *reinterpret_cast<const uint4*>(
                        smem + OFF_SB + swzoff((nt0 + nt) * 8 + g, q, ks));
                    uint32_t bh[2] = {bv.x, bv.y};
                    uint32_t bl[2] = {bv.z, bv.w};
                    mma_bf16(acc[nt], ah, bh);
                    mma_bf16(acc[nt], ah, bl);
                    mma_bf16(acc[nt], al, bh);
                }
            }

            // ---- epilogue: partial logits over this e-half -> sPart ----
            #pragma unroll
            for (int h = 0; h < 2; h++) {
                float pl = 0.0f;
                #pragma unroll
                for (int nt = 0; nt < 4; nt++) {
                    const int e0 = (nt0 + nt) * 8 + 2 * q;
                    float q0 = acc[nt][2 * h + 0] + sWB[e0];
                    float q1 = acc[nt][2 * h + 1] + sWB[e0 + 1];
                    q0 = (q0 >= 0.0f) ? q0 : NEG_SLOPE * q0;
                    q1 = (q1 >= 0.0f) ? q1 : NEG_SLOPE * q1;
                    pl = fmaf(sAW[e0], q0, pl);
                    pl = fmaf(sAW[e0 + 1], q1, pl);
                }
                pl += __shfl_xor_sync(0xffffffffu, pl, 1);
                pl += __shfl_xor_sync(0xffffffffu, pl, 2);
                if (q == 0) sPT[eh * 64 + (2 * p + h) * 8 + g] = pl;
            }
        }
        __syncthreads();

        // ---- combine partials + store logits (+mirror) ----
        if (tx < 64) {
            const float pl = sPT[tx] + sPT[64 + tx];
            const int i = tx >> 3;
            const int j = tx & 7;
            logits[((size_t)b * Nn + bi * 8 + i) * Nn + bj * 8 + j] = pl;
            if (!diag)
                logits[((size_t)b * Nn + bj * 8 + j) * Nn + bi * 8 + i] = pl;
        }
    }
}

// in-place softmax over last dim of logits [B,N,N]; half-warp per row, float4 lanes
__global__ __launch_bounds__(256)
void afm_softmax(float* __restrict__ logits)
{
    const int wid = threadIdx.x >> 5;
    const int lid = threadIdx.x & 31;
    const int h   = lid >> 4;       // row within warp
    const int c   = lid & 15;       // float4 chunk
    const int i   = blockIdx.x * 16 + wid * 2 + h;
    const int b   = blockIdx.y;
    float4* row = reinterpret_cast<float4*>(logits + ((size_t)b * Nn + i) * Nn);
    float4 v = row[c];
    float m = fmaxf(fmaxf(v.x, v.y), fmaxf(v.z, v.w));
    #pragma unroll
    for (int msk = 8; msk >= 1; msk >>= 1)
        m = fmaxf(m, __shfl_xor_sync(0xffffffffu, m, msk));
    float e0 = __expf(v.x - m);
    float e1 = __expf(v.y - m);
    float e2 = __expf(v.z - m);
    float e3 = __expf(v.w - m);
    float s = (e0 + e1) + (e2 + e3);
    #pragma unroll
    for (int msk = 8; msk >= 1; msk >>= 1)
        s += __shfl_xor_sync(0xffffffffu, s, msk);
    const float inv = 1.0f / s;
    row[c] = make_float4(e0 * inv, e1 * inv, e2 * inv, e3 * inv);
}

extern "C" void kernel_launch(void* const* d_in, const int* in_sizes, int n_in,
                              void* d_out, int out_size)
{
    (void)in_sizes; (void)n_in; (void)out_size;
    const float* emb = (const float*)d_in[0];
    const float* wW  = (const float*)d_in[1];
    const float* wb  = (const float*)d_in[2];
    const float* aW  = (const float*)d_in[3];
    // d_in[4] = a_b: constant shift, cancels in softmax

    float* out  = (float*)d_out;
    float* outA = out;                          // logits scratch -> alphas
    float* outV = out + (size_t)Bn * Nn * Nn;

    cudaFuncSetAttribute(afm_pair, cudaFuncAttributeMaxDynamicSharedMemorySize, SMEM_TOTAL);
    dim3 grid1(6, Bn);
    afm_pair<<<grid1, 256, SMEM_TOTAL>>>(emb, wW, wb, aW, outA, outV);
    dim3 grid2(4, Bn);
    afm_softmax<<<grid2, 256>>>(outA);
}